// round 14
// baseline (speedup 1.0000x reference)
#include <cuda_runtime.h>

#define N_GROUPS 5
#define CIN 10
#define NPTS 32
#define COUT 64
#define NACC2 70         // 60 pair-product slots (30 lanes x float2) + 10 moments
#define BN_EPS 1e-3f

// global scratch (no allocations allowed). Zero-initialized at module load;
// finalize_kernel re-zeros g_acc/g_cnt after consuming them, so the
// "zero at entry" invariant holds across graph replays.
__device__ float g_acc[N_GROUPS * NACC2];
__device__ int   g_cnt[N_GROUPS];
__device__ float g_wf[N_GROUPS * CIN * COUT];   // scale-folded weights
__device__ float g_shift[N_GROUPS * COUT];

__device__ __forceinline__ int group_id(int num) {
    if (num < 2) return 0;
    if (num < 3) return 1;
    if (num < 4) return 2;
    if (num < 16) return 3;
    return 4;
}

// lane m in [0,30) -> (i, k): covers products row[i]*row[2k], row[i]*row[2k+1]
// for k = i/2 .. 4.  (For odd i the k=i/2 lane's first product duplicates the
// symmetric entry (i-1,i); finalize skips it.)  First lane of each i-group
// (mm==0) additionally accumulates the first moment sum(row[i]).
__device__ __host__ __forceinline__ void decode_lane(int m, int& i, int& k, int& mm) {
    i = 0; mm = m;
    while (mm >= 5 - i / 2) { mm -= 5 - i / 2; i++; }
    k = i / 2 + mm;
}

// ---------------------------------------------------------------------------
// Pass 1 (R9 exact — best measured): per-group input moments.
// One warp per voxel, warp-private staging, register prefetch.
// Per point: 1 scalar LDS + 1 LDS.64 + 2 FMA per lane (30 active lanes).
// ---------------------------------------------------------------------------
__global__ void __launch_bounds__(256) stats_kernel(
    const float* __restrict__ in, const int* __restrict__ num, int N)
{
    __shared__ __align__(16) float sIn[8][NPTS * CIN];   // per-warp staging
    __shared__ __align__(16) float sAcc[N_GROUPS * NACC2];
    __shared__ int sCnt[N_GROUPS];

    int tid = threadIdx.x;
    for (int k = tid; k < N_GROUPS * NACC2; k += 256) sAcc[k] = 0.f;
    if (tid < N_GROUPS) sCnt[tid] = 0;

    int w = tid >> 5, lane = tid & 31;
    float* sInW = sIn[w];
    float4* dst = (float4*)sInW;

    int iIdx = 0, jOff = 0;
    bool valid = lane < 30, isMom = false;
    if (valid) {
        int i, k, mm;
        decode_lane(lane, i, k, mm);
        iIdx = i; jOff = 2 * k; isMom = (mm == 0);
    }
    __syncthreads();

    int warpGlobal = blockIdx.x * 8 + w;
    int warpStride = gridDim.x * 8;

    // prefetch first voxel into registers
    float4 r0, r1, r2;
    int gNext = 0;
    if (warpGlobal < N) {
        const float4* src = (const float4*)(in + (size_t)warpGlobal * (NPTS * CIN));
        r0 = src[lane];
        r1 = src[lane + 32];
        if (lane < 16) r2 = src[lane + 64];
        gNext = group_id(__ldg(&num[warpGlobal]));
    }

    for (int n = warpGlobal; n < N; n += warpStride) {
        dst[lane]      = r0;
        dst[lane + 32] = r1;
        if (lane < 16) dst[lane + 64] = r2;
        int g = gNext;
        __syncwarp();

        int n2 = n + warpStride;
        if (n2 < N) {
            const float4* src = (const float4*)(in + (size_t)n2 * (NPTS * CIN));
            r0 = src[lane];
            r1 = src[lane + 32];
            if (lane < 16) r2 = src[lane + 64];
            gNext = group_id(__ldg(&num[n2]));
        }

        float2 acc0 = make_float2(0.f, 0.f), acc1 = make_float2(0.f, 0.f);
        float s0 = 0.f, s1 = 0.f;
        #pragma unroll
        for (int p = 0; p < NPTS; p += 2) {
            const float* row = sInW + p * CIN;
            float  xi  = row[iIdx];
            float2 jj  = *(const float2*)(row + jOff);
            acc0.x += xi * jj.x;
            acc0.y += xi * jj.y;
            if (isMom) s0 += xi;

            const float* row1 = row + CIN;
            float  xi1 = row1[iIdx];
            float2 jj1 = *(const float2*)(row1 + jOff);
            acc1.x += xi1 * jj1.x;
            acc1.y += xi1 * jj1.y;
            if (isMom) s1 += xi1;
        }
        if (valid) {
            atomicAdd(&sAcc[g * NACC2 + 2 * lane],     acc0.x + acc1.x);
            atomicAdd(&sAcc[g * NACC2 + 2 * lane + 1], acc0.y + acc1.y);
        }
        if (isMom) atomicAdd(&sAcc[g * NACC2 + 60 + iIdx], s0 + s1);
        if (lane == 0) atomicAdd(&sCnt[g], 1);
        __syncwarp();
    }

    __syncthreads();
    for (int k = tid; k < N_GROUPS * NACC2; k += 256) atomicAdd(&g_acc[k], sAcc[k]);
    if (tid < N_GROUPS) atomicAdd(&g_cnt[tid], sCnt[tid]);
}

// ---------------------------------------------------------------------------
// Finalize (single block!): per (g,c) compute folded weights + shift, then
// re-zero g_acc / g_cnt to restore the invariant for the next replay.
// ---------------------------------------------------------------------------
__global__ void finalize_kernel(const float* __restrict__ W,
                                const float* __restrict__ gamma,
                                const float* __restrict__ beta)
{
    int t = threadIdx.x;
    if (t < N_GROUPS * COUT) {
        int g = t / COUT, c = t % COUT;
        float w[CIN];
        #pragma unroll
        for (int i = 0; i < CIN; i++) w[i] = W[(g * CIN + i) * COUT + c];

        const float* acc = &g_acc[g * NACC2];
        float sum = 0.f;
        #pragma unroll
        for (int i = 0; i < CIN; i++) sum += acc[60 + i] * w[i];

        float sq = 0.f;
        #pragma unroll
        for (int m = 0; m < 30; m++) {
            int i, k, mm;
            decode_lane(m, i, k, mm);
            int j0 = 2 * k, j1 = 2 * k + 1;
            if (j0 >= i) {                 // skip duplicate on odd-i boundary
                float f = (j0 == i) ? 1.f : 2.f;
                sq += f * acc[2 * m] * w[i] * w[j0];
            }
            {
                float f = (j1 == i) ? 1.f : 2.f;
                sq += f * acc[2 * m + 1] * w[i] * w[j1];
            }
        }
        float denom = fmaxf((float)g_cnt[g] * (float)NPTS, 1.f);
        float mean = sum / denom;
        float var  = sq / denom - mean * mean;
        float scale = gamma[t] * rsqrtf(var + BN_EPS);
        g_shift[t] = beta[t] - mean * scale;
        #pragma unroll
        for (int i = 0; i < CIN; i++)
            g_wf[(g * CIN + i) * COUT + c] = w[i] * scale;
    }
    __syncthreads();   // everyone done reading g_acc / g_cnt
    if (t < N_GROUPS * NACC2) g_acc[t] = 0.f;
    if (t < N_GROUPS) g_cnt[t] = 0;
}

// ---------------------------------------------------------------------------
// Pass 2 (R9 kernel, persistent grid): one WARP per voxel, 2 channels/lane,
// all 32 points per lane. Prefetch; __stcs streaming stores; (128,7).
// Grid = 148*7 = 1036 blocks — exactly resident, zero wave transitions,
// ~9.7 voxels per warp so the prefetch pipeline stays primed.
// ---------------------------------------------------------------------------
__global__ void __launch_bounds__(128, 7) main_kernel(
    const float* __restrict__ in, const int* __restrict__ num,
    float* __restrict__ out, int N)
{
    __shared__ __align__(16) float sW[N_GROUPS * CIN * COUT];   // folded weights
    __shared__ __align__(16) float sSh[N_GROUPS * COUT];
    __shared__ __align__(16) float sIn[4][NPTS * CIN];          // per-warp staging

    int tid = threadIdx.x;
    for (int k = tid; k < N_GROUPS * CIN * COUT / 4; k += 128)
        ((float4*)sW)[k] = ((const float4*)g_wf)[k];
    for (int k = tid; k < N_GROUPS * COUT; k += 128) sSh[k] = g_shift[k];
    __syncthreads();

    int warp = tid >> 5, lane = tid & 31;
    int c0 = lane << 1;              // 2 channels per lane
    float* sInW = sIn[warp];
    float4* dst = (float4*)sInW;

    int warpGlobal = blockIdx.x * 4 + warp;
    int warpStride = gridDim.x * 4;

    // prefetch first voxel
    float4 r0, r1, r2;
    int gNext = 0;
    if (warpGlobal < N) {
        const float4* src = (const float4*)(in + (size_t)warpGlobal * (NPTS * CIN));
        r0 = src[lane];
        r1 = src[lane + 32];
        if (lane < 16) r2 = src[lane + 64];
        gNext = group_id(__ldg(&num[warpGlobal]));
    }

    for (int n = warpGlobal; n < N; n += warpStride) {
        dst[lane]      = r0;
        dst[lane + 32] = r1;
        if (lane < 16) dst[lane + 64] = r2;
        int g = gNext;
        __syncwarp();

        int n2 = n + warpStride;
        if (n2 < N) {
            const float4* src = (const float4*)(in + (size_t)n2 * (NPTS * CIN));
            r0 = src[lane];
            r1 = src[lane + 32];
            if (lane < 16) r2 = src[lane + 64];
            gNext = group_id(__ldg(&num[n2]));
        }

        // folded weights + shift into registers (once per voxel)
        float2 w[CIN];
        const float* wp = sW + g * (CIN * COUT) + c0;
        #pragma unroll
        for (int i = 0; i < CIN; i++) w[i] = *(const float2*)(wp + i * COUT);
        float2 sh = *(const float2*)(sSh + g * COUT + c0);

        float mx0 = 0.f, mx1 = 0.f;
        float* outv = out + (size_t)n * (NPTS * 128);

        #pragma unroll
        for (int p = 0; p < NPTS; p++) {
            const float* v = sInW + p * CIN;   // broadcast reads
            float a0 = sh.x, a1 = sh.y;
            #pragma unroll
            for (int i = 0; i < CIN; i++) {
                float vi = v[i];
                a0 += vi * w[i].x;
                a1 += vi * w[i].y;
            }
            float y0 = fmaxf(a0, 0.f);
            float y1 = fmaxf(a1, 0.f);
            mx0 = fmaxf(mx0, y0);
            mx1 = fmaxf(mx1, y1);
            __stcs((float2*)(outv + p * 128 + c0), make_float2(y0, y1));
        }

        // broadcast-max half (lane-private max covers all 32 points)
        float2 mx = make_float2(mx0, mx1);
        float* ob = outv + 64 + c0;
        #pragma unroll
        for (int p = 0; p < NPTS; p++) {
            __stcs((float2*)(ob + p * 128), mx);
        }
        __syncwarp();   // protect sInW before next iteration's staging
    }
}

extern "C" void kernel_launch(void* const* d_in, const int* in_sizes, int n_in,
                              void* d_out, int out_size) {
    const float* inputs = (const float*)d_in[0];
    const int*   num    = (const int*)d_in[1];
    const float* W      = (const float*)d_in[2];
    const float* gamma  = (const float*)d_in[3];
    const float* beta   = (const float*)d_in[4];
    float* out = (float*)d_out;
    int N = in_sizes[1];   // num has one entry per voxel

    stats_kernel<<<1184, 256>>>(inputs, num, N);
    finalize_kernel<<<1, 352>>>(W, gamma, beta);
    main_kernel<<<1036, 128>>>(inputs, num, out, N);
}

// round 15
// speedup vs baseline: 1.0744x; 1.0744x over previous
#include <cuda_runtime.h>

#define N_GROUPS 5
#define CIN 10
#define NPTS 32
#define COUT 64
#define NACC2 70         // 60 pair-product slots (30 lanes x float2) + 10 moments
#define BN_EPS 1e-3f

// global scratch (no allocations allowed). Zero-initialized at module load;
// finalize_kernel re-zeros g_acc/g_cnt after consuming them, so the
// "zero at entry" invariant holds across graph replays.
__device__ float g_acc[N_GROUPS * NACC2];
__device__ int   g_cnt[N_GROUPS];
__device__ float g_wf[N_GROUPS * CIN * COUT];   // scale-folded weights
__device__ float g_shift[N_GROUPS * COUT];

__device__ __forceinline__ int group_id(int num) {
    if (num < 2) return 0;
    if (num < 3) return 1;
    if (num < 4) return 2;
    if (num < 16) return 3;
    return 4;
}

// lane m in [0,30) -> (i, k): covers products row[i]*row[2k], row[i]*row[2k+1]
// for k = i/2 .. 4.  (For odd i the k=i/2 lane's first product duplicates the
// symmetric entry (i-1,i); finalize skips it.)  First lane of each i-group
// (mm==0) additionally accumulates the first moment sum(row[i]).
__device__ __host__ __forceinline__ void decode_lane(int m, int& i, int& k, int& mm) {
    i = 0; mm = m;
    while (mm >= 5 - i / 2) { mm -= 5 - i / 2; i++; }
    k = i / 2 + mm;
}

// ---------------------------------------------------------------------------
// Pass 1: per-group input moments. One warp per voxel, warp-private staging,
// register prefetch. Per point: 1 scalar LDS + 1 LDS.64 + 2 FMA per lane.
// ---------------------------------------------------------------------------
__global__ void __launch_bounds__(256) stats_kernel(
    const float* __restrict__ in, const int* __restrict__ num, int N)
{
    __shared__ __align__(16) float sIn[8][NPTS * CIN];   // per-warp staging
    __shared__ __align__(16) float sAcc[N_GROUPS * NACC2];
    __shared__ int sCnt[N_GROUPS];

    int tid = threadIdx.x;
    for (int k = tid; k < N_GROUPS * NACC2; k += 256) sAcc[k] = 0.f;
    if (tid < N_GROUPS) sCnt[tid] = 0;

    int w = tid >> 5, lane = tid & 31;
    float* sInW = sIn[w];
    float4* dst = (float4*)sInW;

    int iIdx = 0, jOff = 0;
    bool valid = lane < 30, isMom = false;
    if (valid) {
        int i, k, mm;
        decode_lane(lane, i, k, mm);
        iIdx = i; jOff = 2 * k; isMom = (mm == 0);
    }
    __syncthreads();

    int warpGlobal = blockIdx.x * 8 + w;
    int warpStride = gridDim.x * 8;

    // prefetch first voxel into registers
    float4 r0, r1, r2;
    int gNext = 0;
    if (warpGlobal < N) {
        const float4* src = (const float4*)(in + (size_t)warpGlobal * (NPTS * CIN));
        r0 = src[lane];
        r1 = src[lane + 32];
        if (lane < 16) r2 = src[lane + 64];
        gNext = group_id(__ldg(&num[warpGlobal]));
    }

    for (int n = warpGlobal; n < N; n += warpStride) {
        dst[lane]      = r0;
        dst[lane + 32] = r1;
        if (lane < 16) dst[lane + 64] = r2;
        int g = gNext;
        __syncwarp();

        int n2 = n + warpStride;
        if (n2 < N) {
            const float4* src = (const float4*)(in + (size_t)n2 * (NPTS * CIN));
            r0 = src[lane];
            r1 = src[lane + 32];
            if (lane < 16) r2 = src[lane + 64];
            gNext = group_id(__ldg(&num[n2]));
        }

        float2 acc0 = make_float2(0.f, 0.f), acc1 = make_float2(0.f, 0.f);
        float s0 = 0.f, s1 = 0.f;
        #pragma unroll
        for (int p = 0; p < NPTS; p += 2) {
            const float* row = sInW + p * CIN;
            float  xi  = row[iIdx];
            float2 jj  = *(const float2*)(row + jOff);
            acc0.x += xi * jj.x;
            acc0.y += xi * jj.y;
            if (isMom) s0 += xi;

            const float* row1 = row + CIN;
            float  xi1 = row1[iIdx];
            float2 jj1 = *(const float2*)(row1 + jOff);
            acc1.x += xi1 * jj1.x;
            acc1.y += xi1 * jj1.y;
            if (isMom) s1 += xi1;
        }
        if (valid) {
            atomicAdd(&sAcc[g * NACC2 + 2 * lane],     acc0.x + acc1.x);
            atomicAdd(&sAcc[g * NACC2 + 2 * lane + 1], acc0.y + acc1.y);
        }
        if (isMom) atomicAdd(&sAcc[g * NACC2 + 60 + iIdx], s0 + s1);
        if (lane == 0) atomicAdd(&sCnt[g], 1);
        __syncwarp();
    }

    __syncthreads();
    for (int k = tid; k < N_GROUPS * NACC2; k += 256) atomicAdd(&g_acc[k], sAcc[k]);
    if (tid < N_GROUPS) atomicAdd(&g_cnt[tid], sCnt[tid]);
}

// ---------------------------------------------------------------------------
// Finalize (single block!): per (g,c) compute folded weights + shift, then
// re-zero g_acc / g_cnt to restore the invariant for the next replay.
// ---------------------------------------------------------------------------
__global__ void finalize_kernel(const float* __restrict__ W,
                                const float* __restrict__ gamma,
                                const float* __restrict__ beta)
{
    int t = threadIdx.x;
    if (t < N_GROUPS * COUT) {
        int g = t / COUT, c = t % COUT;
        float w[CIN];
        #pragma unroll
        for (int i = 0; i < CIN; i++) w[i] = W[(g * CIN + i) * COUT + c];

        const float* acc = &g_acc[g * NACC2];
        float sum = 0.f;
        #pragma unroll
        for (int i = 0; i < CIN; i++) sum += acc[60 + i] * w[i];

        float sq = 0.f;
        #pragma unroll
        for (int m = 0; m < 30; m++) {
            int i, k, mm;
            decode_lane(m, i, k, mm);
            int j0 = 2 * k, j1 = 2 * k + 1;
            if (j0 >= i) {                 // skip duplicate on odd-i boundary
                float f = (j0 == i) ? 1.f : 2.f;
                sq += f * acc[2 * m] * w[i] * w[j0];
            }
            {
                float f = (j1 == i) ? 1.f : 2.f;
                sq += f * acc[2 * m + 1] * w[i] * w[j1];
            }
        }
        float denom = fmaxf((float)g_cnt[g] * (float)NPTS, 1.f);
        float mean = sum / denom;
        float var  = sq / denom - mean * mean;
        float scale = gamma[t] * rsqrtf(var + BN_EPS);
        g_shift[t] = beta[t] - mean * scale;
        #pragma unroll
        for (int i = 0; i < CIN; i++)
            g_wf[(g * CIN + i) * COUT + c] = w[i] * scale;
    }
    __syncthreads();   // everyone done reading g_acc / g_cnt
    if (t < N_GROUPS * NACC2) g_acc[t] = 0.f;
    if (t < N_GROUPS) g_cnt[t] = 0;
}

// ---------------------------------------------------------------------------
// Pass 2: one WARP per voxel, 2 channels per lane, all 32 points per lane.
// Weights = 20 regs/lane; channel max is lane-private (no shuffles).
// Register prefetch of the next voxel; __stcs streaming stores; (128,7);
// grid 2960 (≈2.9 waves — measured faster than exactly-resident).
// ---------------------------------------------------------------------------
__global__ void __launch_bounds__(128, 7) main_kernel(
    const float* __restrict__ in, const int* __restrict__ num,
    float* __restrict__ out, int N)
{
    __shared__ __align__(16) float sW[N_GROUPS * CIN * COUT];   // folded weights
    __shared__ __align__(16) float sSh[N_GROUPS * COUT];
    __shared__ __align__(16) float sIn[4][NPTS * CIN];          // per-warp staging

    int tid = threadIdx.x;
    for (int k = tid; k < N_GROUPS * CIN * COUT / 4; k += 128)
        ((float4*)sW)[k] = ((const float4*)g_wf)[k];
    for (int k = tid; k < N_GROUPS * COUT; k += 128) sSh[k] = g_shift[k];
    __syncthreads();

    int warp = tid >> 5, lane = tid & 31;
    int c0 = lane << 1;              // 2 channels per lane
    float* sInW = sIn[warp];
    float4* dst = (float4*)sInW;

    int warpGlobal = blockIdx.x * 4 + warp;
    int warpStride = gridDim.x * 4;

    // prefetch first voxel
    float4 r0, r1, r2;
    int gNext = 0;
    if (warpGlobal < N) {
        const float4* src = (const float4*)(in + (size_t)warpGlobal * (NPTS * CIN));
        r0 = src[lane];
        r1 = src[lane + 32];
        if (lane < 16) r2 = src[lane + 64];
        gNext = group_id(__ldg(&num[warpGlobal]));
    }

    for (int n = warpGlobal; n < N; n += warpStride) {
        dst[lane]      = r0;
        dst[lane + 32] = r1;
        if (lane < 16) dst[lane + 64] = r2;
        int g = gNext;
        __syncwarp();

        int n2 = n + warpStride;
        if (n2 < N) {
            const float4* src = (const float4*)(in + (size_t)n2 * (NPTS * CIN));
            r0 = src[lane];
            r1 = src[lane + 32];
            if (lane < 16) r2 = src[lane + 64];
            gNext = group_id(__ldg(&num[n2]));
        }

        // folded weights + shift into registers (once per voxel)
        float2 w[CIN];
        const float* wp = sW + g * (CIN * COUT) + c0;
        #pragma unroll
        for (int i = 0; i < CIN; i++) w[i] = *(const float2*)(wp + i * COUT);
        float2 sh = *(const float2*)(sSh + g * COUT + c0);

        float mx0 = 0.f, mx1 = 0.f;
        float* outv = out + (size_t)n * (NPTS * 128);

        #pragma unroll
        for (int p = 0; p < NPTS; p++) {
            const float* v = sInW + p * CIN;   // broadcast reads
            float a0 = sh.x, a1 = sh.y;
            #pragma unroll
            for (int i = 0; i < CIN; i++) {
                float vi = v[i];
                a0 += vi * w[i].x;
                a1 += vi * w[i].y;
            }
            float y0 = fmaxf(a0, 0.f);
            float y1 = fmaxf(a1, 0.f);
            mx0 = fmaxf(mx0, y0);
            mx1 = fmaxf(mx1, y1);
            __stcs((float2*)(outv + p * 128 + c0), make_float2(y0, y1));
        }

        // broadcast-max half (lane-private max covers all 32 points)
        float2 mx = make_float2(mx0, mx1);
        float* ob = outv + 64 + c0;
        #pragma unroll
        for (int p = 0; p < NPTS; p++) {
            __stcs((float2*)(ob + p * 128), mx);
        }
        __syncwarp();   // protect sInW before next iteration's staging
    }
}

extern "C" void kernel_launch(void* const* d_in, const int* in_sizes, int n_in,
                              void* d_out, int out_size) {
    const float* inputs = (const float*)d_in[0];
    const int*   num    = (const int*)d_in[1];
    const float* W      = (const float*)d_in[2];
    const float* gamma  = (const float*)d_in[3];
    const float* beta   = (const float*)d_in[4];
    float* out = (float*)d_out;
    int N = in_sizes[1];   // num has one entry per voxel

    stats_kernel<<<1184, 256>>>(inputs, num, N);
    finalize_kernel<<<1, 352>>>(W, gamma, beta);
    main_kernel<<<2960, 128>>>(inputs, num, out, N);
}